// round 1
// baseline (speedup 1.0000x reference)
#include <cuda_runtime.h>
#include <cuda_bf16.h>
#include <mma.h>

using namespace nvcuda;

#define B_DIM 4
#define S_DIM 4096
#define E_DIM 256
#define BS_DIM (B_DIM * S_DIM)

// ---------------- scratch (static __device__, no allocations) ----------------
__device__ __nv_bfloat16 g_x_bf[BS_DIM * E_DIM];                  // 8 MB
__device__ __nv_bfloat16 g_Wq_bf[E_DIM * E_DIM];
__device__ __nv_bfloat16 g_Wk_bf[E_DIM * E_DIM];
__device__ __nv_bfloat16 g_q[BS_DIM * E_DIM];                     // 8 MB
__device__ __nv_bfloat16 g_k[BS_DIM * E_DIM];                     // 8 MB
__device__ __nv_bfloat16 g_E[(size_t)B_DIM * S_DIM * S_DIM];      // 134 MB exp-scores
__device__ float g_Z[B_DIM * S_DIM];                              // softmax row sums
__device__ float g_u[B_DIM * S_DIM];                              // column means of attn
__device__ float g_y[B_DIM * E_DIM];                              // u^T x

// ---------------- fp32 -> bf16 conversion ----------------
__global__ void convert_kernel(const float* __restrict__ x,
                               const float* __restrict__ Wq,
                               const float* __restrict__ Wk) {
    int tid = blockIdx.x * blockDim.x + threadIdx.x;
    int stride = gridDim.x * blockDim.x;
    for (int i = tid; i < BS_DIM * E_DIM; i += stride)
        g_x_bf[i] = __float2bfloat16(x[i]);
    if (tid < E_DIM * E_DIM) {
        g_Wq_bf[tid] = __float2bfloat16(Wq[tid]);
        g_Wk_bf[tid] = __float2bfloat16(Wk[tid]);
    }
}

// ---------------- zero accumulators (must run every launch) ----------------
__global__ void init_kernel() {
    int tid = blockIdx.x * blockDim.x + threadIdx.x;
    if (tid < B_DIM * S_DIM) { g_Z[tid] = 0.f; g_u[tid] = 0.f; }
    if (tid < B_DIM * E_DIM) g_y[tid] = 0.f;
}

// ---------------- Q/K projections: q = bf16(x @ W + b) ----------------
// Block tile 128x64, K=256 in 4 chunks of 64. 8 warps (4x2), warp tile 32x32.
__global__ void __launch_bounds__(256) proj_kernel(const float* __restrict__ bq,
                                                   const float* __restrict__ bk) {
    constexpr int BM = 128, BN = 64, BK = 64;
    __shared__ __align__(32) unsigned char smbuf[BM * 72 * 4];  // 36864 B
    __nv_bfloat16 (*smA)[80] = reinterpret_cast<__nv_bfloat16(*)[80]>(smbuf);
    __nv_bfloat16 (*smB)[80] = reinterpret_cast<__nv_bfloat16(*)[80]>(smbuf + BM * 80 * 2);
    float (*stage)[72] = reinterpret_cast<float(*)[72]>(smbuf);

    const int m0 = blockIdx.x * BM;
    const int n0 = blockIdx.y * BN;
    const int which = blockIdx.z;
    const __nv_bfloat16* Ag = g_x_bf;
    const __nv_bfloat16* Bg = which ? g_Wk_bf : g_Wq_bf;
    const float* bias = which ? bk : bq;
    __nv_bfloat16* outp = which ? g_k : g_q;

    const int tid = threadIdx.x;
    const int warp = tid >> 5;
    const int wm = warp >> 1, wn = warp & 1;

    wmma::fragment<wmma::accumulator, 16, 16, 16, float> acc[2][2];
    for (int i = 0; i < 2; i++)
        for (int j = 0; j < 2; j++) wmma::fill_fragment(acc[i][j], 0.f);

    for (int k0 = 0; k0 < E_DIM; k0 += BK) {
        #pragma unroll
        for (int it = 0; it < 4; ++it) {   // A: 128x64 = 1024 uint4
            int idx = tid + it * 256;
            int r = idx >> 3, g = idx & 7;
            *reinterpret_cast<uint4*>(&smA[r][g * 8]) =
                *reinterpret_cast<const uint4*>(&Ag[(size_t)(m0 + r) * E_DIM + k0 + g * 8]);
        }
        #pragma unroll
        for (int it = 0; it < 2; ++it) {   // B: 64x64 = 512 uint4
            int idx = tid + it * 256;
            int r = idx >> 3, g = idx & 7;
            *reinterpret_cast<uint4*>(&smB[r][g * 8]) =
                *reinterpret_cast<const uint4*>(&Bg[(size_t)(k0 + r) * E_DIM + n0 + g * 8]);
        }
        __syncthreads();
        #pragma unroll
        for (int kk = 0; kk < BK; kk += 16) {
            wmma::fragment<wmma::matrix_a, 16, 16, 16, __nv_bfloat16, wmma::row_major> af[2];
            wmma::fragment<wmma::matrix_b, 16, 16, 16, __nv_bfloat16, wmma::row_major> bfm[2];
            for (int i = 0; i < 2; i++)
                wmma::load_matrix_sync(af[i], &smA[wm * 32 + i * 16][kk], 80);
            for (int j = 0; j < 2; j++)
                wmma::load_matrix_sync(bfm[j], &smB[kk][wn * 32 + j * 16], 80);
            for (int i = 0; i < 2; i++)
                for (int j = 0; j < 2; j++)
                    wmma::mma_sync(acc[i][j], af[i], bfm[j], acc[i][j]);
        }
        __syncthreads();
    }
    for (int i = 0; i < 2; i++)
        for (int j = 0; j < 2; j++)
            wmma::store_matrix_sync(&stage[wm * 32 + i * 16][wn * 32 + j * 16],
                                    acc[i][j], 72, wmma::mem_row_major);
    __syncthreads();
    int r = tid >> 1, ch = tid & 1;
    #pragma unroll 8
    for (int c = 0; c < 32; ++c) {
        int col = ch * 32 + c;
        float v = stage[r][col] + bias[n0 + col];
        outp[(size_t)(m0 + r) * E_DIM + n0 + col] = __float2bfloat16(v);
    }
}

// ---------------- scores: E = exp(q k^T / 16), fused row sums -> g_Z ----------------
__global__ void __launch_bounds__(256) scores_kernel() {
    constexpr int BM = 128, BN = 64, BK = 64;
    __shared__ __align__(32) unsigned char smbuf[BM * 72 * 4];
    __nv_bfloat16 (*smA)[80] = reinterpret_cast<__nv_bfloat16(*)[80]>(smbuf);
    __nv_bfloat16 (*smB)[80] = reinterpret_cast<__nv_bfloat16(*)[80]>(smbuf + BM * 80 * 2);
    float (*stage)[72] = reinterpret_cast<float(*)[72]>(smbuf);

    const int n0 = blockIdx.x * BN;
    const int m0 = blockIdx.y * BM;
    const int b  = blockIdx.z;
    const __nv_bfloat16* Ag = g_q + (size_t)b * S_DIM * E_DIM;
    const __nv_bfloat16* Bg = g_k + (size_t)b * S_DIM * E_DIM;

    const int tid = threadIdx.x;
    const int warp = tid >> 5;
    const int wm = warp >> 1, wn = warp & 1;

    wmma::fragment<wmma::accumulator, 16, 16, 16, float> acc[2][2];
    for (int i = 0; i < 2; i++)
        for (int j = 0; j < 2; j++) wmma::fill_fragment(acc[i][j], 0.f);

    for (int k0 = 0; k0 < E_DIM; k0 += BK) {
        #pragma unroll
        for (int it = 0; it < 4; ++it) {   // A = q tile 128x64
            int idx = tid + it * 256;
            int r = idx >> 3, g = idx & 7;
            *reinterpret_cast<uint4*>(&smA[r][g * 8]) =
                *reinterpret_cast<const uint4*>(&Ag[(size_t)(m0 + r) * E_DIM + k0 + g * 8]);
        }
        #pragma unroll
        for (int it = 0; it < 2; ++it) {   // B = k tile 64 rows(t) x 64 cols(e)
            int idx = tid + it * 256;
            int r = idx >> 3, g = idx & 7;
            *reinterpret_cast<uint4*>(&smB[r][g * 8]) =
                *reinterpret_cast<const uint4*>(&Bg[(size_t)(n0 + r) * E_DIM + k0 + g * 8]);
        }
        __syncthreads();
        #pragma unroll
        for (int kk = 0; kk < BK; kk += 16) {
            wmma::fragment<wmma::matrix_a, 16, 16, 16, __nv_bfloat16, wmma::row_major> af[2];
            wmma::fragment<wmma::matrix_b, 16, 16, 16, __nv_bfloat16, wmma::col_major> bfm[2];
            for (int i = 0; i < 2; i++)
                wmma::load_matrix_sync(af[i], &smA[wm * 32 + i * 16][kk], 80);
            for (int j = 0; j < 2; j++)   // col-major view: B[k][n] = smB[n][k]
                wmma::load_matrix_sync(bfm[j], &smB[wn * 32 + j * 16][kk], 80);
            for (int i = 0; i < 2; i++)
                for (int j = 0; j < 2; j++)
                    wmma::mma_sync(acc[i][j], af[i], bfm[j], acc[i][j]);
        }
        __syncthreads();
    }
    for (int i = 0; i < 2; i++)
        for (int j = 0; j < 2; j++)
            wmma::store_matrix_sync(&stage[wm * 32 + i * 16][wn * 32 + j * 16],
                                    acc[i][j], 72, wmma::mem_row_major);
    __syncthreads();

    // epilogue: exp(score/16), vectorized bf16 store, fused row sums
    int r = tid >> 1, ch = tid & 1;
    float rs = 0.f;
    size_t rowbase = ((size_t)b * S_DIM + m0 + r) * S_DIM + n0 + ch * 32;
    #pragma unroll
    for (int g = 0; g < 4; ++g) {
        uint4 pkt;
        __nv_bfloat162* p2 = reinterpret_cast<__nv_bfloat162*>(&pkt);
        #pragma unroll
        for (int j = 0; j < 4; ++j) {
            float v0 = __expf(stage[r][ch * 32 + g * 8 + 2 * j]     * 0.0625f);
            float v1 = __expf(stage[r][ch * 32 + g * 8 + 2 * j + 1] * 0.0625f);
            rs += v0 + v1;
            p2[j] = __floats2bfloat162_rn(v0, v1);
        }
        *reinterpret_cast<uint4*>(&g_E[rowbase + g * 8]) = pkt;
    }
    rs += __shfl_xor_sync(0xffffffffu, rs, 1);
    if (ch == 0) atomicAdd(&g_Z[b * S_DIM + m0 + r], rs);
}

// ---------------- u[b,t] = (1/S) * sum_s E[b,s,t] / Z[b,s] ----------------
__global__ void __launch_bounds__(256) colreduce_kernel() {
    const int b  = blockIdx.z;
    const int s0 = blockIdx.y * 512;
    const int t  = blockIdx.x * 512 + threadIdx.x * 2;
    __shared__ float invZ[512];
    for (int i = threadIdx.x; i < 512; i += 256)
        invZ[i] = 1.f / g_Z[b * S_DIM + s0 + i];
    __syncthreads();
    float a0 = 0.f, a1 = 0.f;
    const __nv_bfloat16* Ep = g_E + ((size_t)b * S_DIM + s0) * S_DIM + t;
    #pragma unroll 4
    for (int s = 0; s < 512; ++s) {
        __nv_bfloat162 e2 = *reinterpret_cast<const __nv_bfloat162*>(&Ep[(size_t)s * S_DIM]);
        float2 f = __bfloat1622float2(e2);
        a0 += f.x * invZ[s];
        a1 += f.y * invZ[s];
    }
    const float sc = 1.f / S_DIM;
    atomicAdd(&g_u[b * S_DIM + t],     a0 * sc);
    atomicAdd(&g_u[b * S_DIM + t + 1], a1 * sc);
}

// ---------------- y[b,:] = sum_t u[b,t] * x[b,t,:]  (fp32-exact V path) ----------------
__global__ void __launch_bounds__(256) pool_kernel(const float* __restrict__ x) {
    const int b = blockIdx.y, seg = blockIdx.x;
    const int e = threadIdx.x;
    __shared__ float us[256];
    us[e] = g_u[b * S_DIM + seg * 256 + e];
    __syncthreads();
    float acc = 0.f;
    const float* xp = x + ((size_t)b * S_DIM + seg * 256) * E_DIM + e;
    #pragma unroll 8
    for (int tt = 0; tt < 256; ++tt) acc += us[tt] * xp[(size_t)tt * E_DIM];
    atomicAdd(&g_y[b * E_DIM + e], acc);
}

// ---------------- out[b,:] = y[b,:] @ Wv + bv ----------------
__global__ void __launch_bounds__(256) out_kernel(const float* __restrict__ Wv,
                                                  const float* __restrict__ bv,
                                                  float* __restrict__ out) {
    const int b = blockIdx.x, e = threadIdx.x;
    __shared__ float ys[256];
    ys[e] = g_y[b * E_DIM + e];
    __syncthreads();
    float acc = 0.f;
    #pragma unroll 8
    for (int j = 0; j < 256; ++j) acc += ys[j] * Wv[j * E_DIM + e];
    out[b * E_DIM + e] = acc + bv[e];
}

// ---------------- launch ----------------
extern "C" void kernel_launch(void* const* d_in, const int* in_sizes, int n_in,
                              void* d_out, int out_size) {
    (void)in_sizes; (void)n_in; (void)out_size;
    const float* x  = (const float*)d_in[0];
    const float* Wq = (const float*)d_in[1];
    const float* bq = (const float*)d_in[2];
    const float* Wk = (const float*)d_in[3];
    const float* bk = (const float*)d_in[4];
    const float* Wv = (const float*)d_in[5];
    const float* bv = (const float*)d_in[6];
    float* out = (float*)d_out;

    convert_kernel<<<8192, 256>>>(x, Wq, Wk);
    init_kernel<<<64, 256>>>();
    proj_kernel<<<dim3(BS_DIM / 128, E_DIM / 64, 2), 256>>>(bq, bk);
    scores_kernel<<<dim3(S_DIM / 64, S_DIM / 128, B_DIM), 256>>>();
    colreduce_kernel<<<dim3(S_DIM / 512, S_DIM / 512, B_DIM), 256>>>();
    pool_kernel<<<dim3(S_DIM / 256, B_DIM), 256>>>(x);
    out_kernel<<<B_DIM, 256>>>(Wv, bv, out);
}

// round 3
// speedup vs baseline: 1.5635x; 1.5635x over previous
#include <cuda_runtime.h>
#include <cuda_bf16.h>
#include <cstdint>

#define B_DIM 4
#define S_DIM 4096
#define E_DIM 256
#define BS_DIM (B_DIM * S_DIM)

// ---------------- scratch (static __device__, no allocations) ----------------
__device__ __nv_bfloat16 g_x_bf[BS_DIM * E_DIM];                  // 8 MB
__device__ __nv_bfloat16 g_WqT[E_DIM * E_DIM];                    // W^T bf16
__device__ __nv_bfloat16 g_WkT[E_DIM * E_DIM];
__device__ __nv_bfloat16 g_q[BS_DIM * E_DIM];                     // 8 MB
__device__ __nv_bfloat16 g_k[BS_DIM * E_DIM];                     // 8 MB
__device__ __nv_bfloat16 g_E[(size_t)B_DIM * S_DIM * S_DIM];      // 134 MB exp-scores
__device__ float g_Z[B_DIM * S_DIM];                              // softmax row sums
__device__ float g_u[B_DIM * S_DIM];                              // column means of attn
__device__ float g_y[B_DIM * E_DIM];                              // u^T x

// ================= low-level helpers =================
__device__ __forceinline__ uint32_t smem_u32(const void* p) {
    uint32_t a;
    asm("{ .reg .u64 t; cvta.to.shared.u64 t, %1; cvt.u32.u64 %0, t; }" : "=r"(a) : "l"(p));
    return a;
}

__device__ __forceinline__ void ldsm4(uint32_t (&r)[4], uint32_t addr) {
    asm volatile("ldmatrix.sync.aligned.m8n8.x4.shared.b16 {%0,%1,%2,%3}, [%4];"
                 : "=r"(r[0]), "=r"(r[1]), "=r"(r[2]), "=r"(r[3]) : "r"(addr));
}

__device__ __forceinline__ void mma16816(float (&d)[4], const uint32_t (&a)[4],
                                         uint32_t b0, uint32_t b1) {
    asm volatile("mma.sync.aligned.m16n8k16.row.col.f32.bf16.bf16.f32 "
                 "{%0,%1,%2,%3}, {%4,%5,%6,%7}, {%8,%9}, {%0,%1,%2,%3};"
                 : "+f"(d[0]), "+f"(d[1]), "+f"(d[2]), "+f"(d[3])
                 : "r"(a[0]), "r"(a[1]), "r"(a[2]), "r"(a[3]), "r"(b0), "r"(b1));
}

// swizzled address inside a 128-row x 256-col bf16 tile (blocked SW128 atoms):
// atom = 8 rows x 128B; atom grid = 16 (rows) x 4 (col-chunks of 64 elems)
__device__ __forceinline__ uint32_t swz128(uint32_t base, int r, int c16) {
    return base + (((uint32_t)(c16 >> 3)) << 14) + (((uint32_t)(r >> 3)) << 10)
                + (((uint32_t)(r & 7)) << 7) + (((uint32_t)((c16 ^ r) & 7)) << 4);
}

// Load a 128x256-bf16 tile (64KB) into the swizzled layout via cp.async (16B chunks).
__device__ __forceinline__ void load_tile_async(uint32_t sm_base,
                                                const __nv_bfloat16* __restrict__ src,
                                                int tid) {
    #pragma unroll
    for (int it = 0; it < 16; ++it) {
        int idx = it * 256 + tid;          // 0..4095 16B chunks
        int r = idx >> 5;                  // row 0..127
        int g = idx & 31;                  // chunk 0..31
        uint32_t dst = swz128(sm_base, r, g);
        const void* gp = (const void*)(src + (size_t)r * E_DIM + g * 8);
        asm volatile("cp.async.cg.shared.global [%0], [%1], 16;" :: "r"(dst), "l"(gp));
    }
}
#define CPASYNC_COMMIT() asm volatile("cp.async.commit_group;" ::: "memory")
#define CPASYNC_WAIT0() asm volatile("cp.async.wait_group 0;" ::: "memory")
#define CPASYNC_WAIT1() asm volatile("cp.async.wait_group 1;" ::: "memory")

// 128x128x256 bf16 MMA: acc[4][4][4] += A(128x256) * B(128x256)^T, warp tile 64x32
__device__ __forceinline__ void mma_tile(uint32_t Ab, uint32_t Bb, float (&acc)[4][4][4],
                                         int mw, int nw, int lane) {
    const int lane15 = lane & 15, laneh = lane >> 4;
    #pragma unroll
    for (int ks = 0; ks < 16; ++ks) {
        const int c16 = ks * 2 + laneh;
        uint32_t a[4][4], bf[2][4];
        #pragma unroll
        for (int i = 0; i < 4; ++i)
            ldsm4(a[i], swz128(Ab, mw + i * 16 + lane15, c16));
        #pragma unroll
        for (int j2 = 0; j2 < 2; ++j2)
            ldsm4(bf[j2], swz128(Bb, nw + j2 * 16 + lane15, c16));
        #pragma unroll
        for (int i = 0; i < 4; ++i)
            #pragma unroll
            for (int j = 0; j < 4; ++j)
                mma16816(acc[i][j], a[i], bf[j >> 1][j & 1], bf[j >> 1][(j & 1) + 2]);
    }
}

// ---------------- fp32 -> bf16 conversion (+ W transposes) ----------------
__global__ void convert_kernel(const float* __restrict__ x,
                               const float* __restrict__ Wq,
                               const float* __restrict__ Wk) {
    int tid = blockIdx.x * blockDim.x + threadIdx.x;
    int stride = gridDim.x * blockDim.x;
    for (int i = tid; i < BS_DIM * E_DIM; i += stride)
        g_x_bf[i] = __float2bfloat16(x[i]);
    if (tid < E_DIM * E_DIM) {
        int k = tid >> 8, n = tid & 255;
        g_WqT[n * E_DIM + k] = __float2bfloat16(Wq[tid]);
        g_WkT[n * E_DIM + k] = __float2bfloat16(Wk[tid]);
    }
}

// ---------------- zero accumulators ----------------
__global__ void init_kernel() {
    int tid = blockIdx.x * blockDim.x + threadIdx.x;
    if (tid < B_DIM * S_DIM) { g_Z[tid] = 0.f; g_u[tid] = 0.f; }
    if (tid < B_DIM * E_DIM) g_y[tid] = 0.f;
}

// ---------------- Q/K projections: out = bf16(x @ W + b) ----------------
// grid (BS/128, 2, 2): (m-block, n-block, which). One-shot tile, K=256.
#define PROJ_SMEM (131072 + 1024)
__global__ void __launch_bounds__(256) proj_tc_kernel(const float* __restrict__ bq,
                                                      const float* __restrict__ bk) {
    extern __shared__ char dynsm[];
    __shared__ float sbias[128];
    const uint32_t base = (smem_u32(dynsm) + 1023u) & ~1023u;
    const uint32_t Ab = base, Bb = base + 65536u;

    const int tid = threadIdx.x;
    const int lane = tid & 31, wid = tid >> 5;
    const int mw = (wid & 1) * 64, nw = (wid >> 1) * 32;
    const int m0 = blockIdx.x * 128, n0 = blockIdx.y * 128;
    const int which = blockIdx.z;

    const __nv_bfloat16* WT = which ? g_WkT : g_WqT;
    const float* bias = which ? bk : bq;
    __nv_bfloat16* outp = which ? g_k : g_q;

    if (tid < 128) sbias[tid] = bias[n0 + tid];
    load_tile_async(Ab, g_x_bf + (size_t)m0 * E_DIM, tid);
    load_tile_async(Bb, WT + (size_t)n0 * E_DIM, tid);
    CPASYNC_COMMIT();
    CPASYNC_WAIT0();
    __syncthreads();

    float acc[4][4][4];
    #pragma unroll
    for (int i = 0; i < 4; ++i)
        #pragma unroll
        for (int j = 0; j < 4; ++j)
            #pragma unroll
            for (int v = 0; v < 4; ++v) acc[i][j][v] = 0.f;

    mma_tile(Ab, Bb, acc, mw, nw, lane);

    #pragma unroll
    for (int i = 0; i < 4; ++i) {
        #pragma unroll
        for (int h = 0; h < 2; ++h) {
            const int r = m0 + mw + i * 16 + (lane >> 2) + h * 8;
            #pragma unroll
            for (int j = 0; j < 4; ++j) {
                const int cl = nw + j * 8 + (lane & 3) * 2;
                float v0 = acc[i][j][2 * h]     + sbias[cl];
                float v1 = acc[i][j][2 * h + 1] + sbias[cl + 1];
                *reinterpret_cast<__nv_bfloat162*>(&outp[(size_t)r * E_DIM + n0 + cl]) =
                    __floats2bfloat162_rn(v0, v1);
            }
        }
    }
}

// ---------------- scores: E = exp(q k^T / 16), fused row sums -> g_Z ----------------
// grid (32, 4): (m-block of 128 rows, batch). Loops 32 n-tiles of 128 cols.
// SMEM: A 64KB resident + B double-buffered 2x64KB.
#define SCORES_SMEM (196608 + 1024)
__global__ void __launch_bounds__(256) scores_mma_kernel() {
    extern __shared__ char dynsm[];
    const uint32_t base = (smem_u32(dynsm) + 1023u) & ~1023u;
    const uint32_t Ab = base;
    const uint32_t Bbuf[2] = { base + 65536u, base + 131072u };

    const int tid = threadIdx.x;
    const int lane = tid & 31, wid = tid >> 5;
    const int mw = (wid & 1) * 64, nw = (wid >> 1) * 32;
    const int m0 = blockIdx.x * 128;
    const int b = blockIdx.y;

    const __nv_bfloat16* Aq = g_q + (size_t)b * S_DIM * E_DIM;
    const __nv_bfloat16* Bk = g_k + (size_t)b * S_DIM * E_DIM;

    load_tile_async(Ab, Aq + (size_t)m0 * E_DIM, tid);
    load_tile_async(Bbuf[0], Bk, tid);
    CPASYNC_COMMIT();

    float rs[8];
    #pragma unroll
    for (int i = 0; i < 8; ++i) rs[i] = 0.f;

    const float SCALE = 0.09016844f;  // log2(e) / 16

    #pragma unroll 1
    for (int n = 0; n < 32; ++n) {
        if (n + 1 < 32) {
            load_tile_async(Bbuf[(n + 1) & 1], Bk + (size_t)(n + 1) * 128 * E_DIM, tid);
            CPASYNC_COMMIT();
            CPASYNC_WAIT1();
        } else {
            CPASYNC_WAIT0();
        }
        __syncthreads();

        float acc[4][4][4];
        #pragma unroll
        for (int i = 0; i < 4; ++i)
            #pragma unroll
            for (int j = 0; j < 4; ++j)
                #pragma unroll
                for (int v = 0; v < 4; ++v) acc[i][j][v] = 0.f;

        mma_tile(Ab, Bbuf[n & 1], acc, mw, nw, lane);

        // epilogue: exp(score/16) -> bf16 store + row-sum accumulation
        #pragma unroll
        for (int i = 0; i < 4; ++i) {
            #pragma unroll
            for (int h = 0; h < 2; ++h) {
                const int r = m0 + mw + i * 16 + (lane >> 2) + h * 8;
                const size_t rowb = ((size_t)b * S_DIM + r) * S_DIM
                                  + (size_t)n * 128 + nw + (lane & 3) * 2;
                float partial = 0.f;
                #pragma unroll
                for (int j = 0; j < 4; ++j) {
                    float v0, v1;
                    asm("ex2.approx.ftz.f32 %0, %1;" : "=f"(v0) : "f"(acc[i][j][2 * h] * SCALE));
                    asm("ex2.approx.ftz.f32 %0, %1;" : "=f"(v1) : "f"(acc[i][j][2 * h + 1] * SCALE));
                    partial += v0 + v1;
                    *reinterpret_cast<__nv_bfloat162*>(&g_E[rowb + j * 8]) =
                        __floats2bfloat162_rn(v0, v1);
                }
                rs[i * 2 + h] += partial;
            }
        }
        __syncthreads();
    }

    // reduce row sums over the 4 lanes sharing a row, then atomically publish
    #pragma unroll
    for (int i = 0; i < 8; ++i) {
        rs[i] += __shfl_xor_sync(0xffffffffu, rs[i], 1);
        rs[i] += __shfl_xor_sync(0xffffffffu, rs[i], 2);
    }
    if ((lane & 3) == 0) {
        #pragma unroll
        for (int i = 0; i < 8; ++i) {
            const int r = m0 + mw + (i >> 1) * 16 + (i & 1) * 8 + (lane >> 2);
            atomicAdd(&g_Z[b * S_DIM + r], rs[i]);
        }
    }
}

// ---------------- u[b,t] = (1/S) * sum_s E[b,s,t] / Z[b,s] ----------------
__global__ void __launch_bounds__(256) colreduce_kernel() {
    const int b  = blockIdx.z;
    const int s0 = blockIdx.y * 256;
    const int t0 = blockIdx.x * 2048 + threadIdx.x * 8;
    __shared__ float invZ[256];
    invZ[threadIdx.x] = 1.f / g_Z[b * S_DIM + s0 + threadIdx.x];
    __syncthreads();
    float a[8] = {0.f, 0.f, 0.f, 0.f, 0.f, 0.f, 0.f, 0.f};
    const __nv_bfloat16* Ep = g_E + ((size_t)b * S_DIM + s0) * S_DIM + t0;
    #pragma unroll 8
    for (int s = 0; s < 256; ++s) {
        uint4 pkt = *reinterpret_cast<const uint4*>(&Ep[(size_t)s * S_DIM]);
        const __nv_bfloat162* p2 = reinterpret_cast<const __nv_bfloat162*>(&pkt);
        float w = invZ[s];
        #pragma unroll
        for (int j = 0; j < 4; ++j) {
            float2 f = __bfloat1622float2(p2[j]);
            a[2 * j]     += f.x * w;
            a[2 * j + 1] += f.y * w;
        }
    }
    const float sc = 1.f / S_DIM;
    #pragma unroll
    for (int j = 0; j < 8; ++j)
        atomicAdd(&g_u[b * S_DIM + t0 + j], a[j] * sc);
}

// ---------------- y[b,:] = sum_t u[b,t] * x[b,t,:]  (fp32-exact V path) ----------------
__global__ void __launch_bounds__(256) pool_kernel(const float* __restrict__ x) {
    const int b = blockIdx.y, seg = blockIdx.x;
    const int e = threadIdx.x;
    __shared__ float us[256];
    us[e] = g_u[b * S_DIM + seg * 256 + e];
    __syncthreads();
    float acc = 0.f;
    const float* xp = x + ((size_t)b * S_DIM + seg * 256) * E_DIM + e;
    #pragma unroll 8
    for (int tt = 0; tt < 256; ++tt) acc += us[tt] * xp[(size_t)tt * E_DIM];
    atomicAdd(&g_y[b * E_DIM + e], acc);
}

// ---------------- out[b,:] = y[b,:] @ Wv + bv ----------------
__global__ void __launch_bounds__(256) out_kernel(const float* __restrict__ Wv,
                                                  const float* __restrict__ bv,
                                                  float* __restrict__ out) {
    const int b = blockIdx.x, e = threadIdx.x;
    __shared__ float ys[256];
    ys[e] = g_y[b * E_DIM + e];
    __syncthreads();
    float acc = 0.f;
    #pragma unroll 8
    for (int j = 0; j < 256; ++j) acc += ys[j] * Wv[j * E_DIM + e];
    out[b * E_DIM + e] = acc + bv[e];
}

// ---------------- launch ----------------
extern "C" void kernel_launch(void* const* d_in, const int* in_sizes, int n_in,
                              void* d_out, int out_size) {
    (void)in_sizes; (void)n_in; (void)out_size;
    const float* x  = (const float*)d_in[0];
    const float* Wq = (const float*)d_in[1];
    const float* bq = (const float*)d_in[2];
    const float* Wk = (const float*)d_in[3];
    const float* bk = (const float*)d_in[4];
    const float* Wv = (const float*)d_in[5];
    const float* bv = (const float*)d_in[6];
    float* out = (float*)d_out;

    cudaFuncSetAttribute(scores_mma_kernel,
                         cudaFuncAttributeMaxDynamicSharedMemorySize, SCORES_SMEM);
    cudaFuncSetAttribute(proj_tc_kernel,
                         cudaFuncAttributeMaxDynamicSharedMemorySize, PROJ_SMEM);

    convert_kernel<<<2048, 256>>>(x, Wq, Wk);
    init_kernel<<<64, 256>>>();
    proj_tc_kernel<<<dim3(BS_DIM / 128, 2, 2), 256, PROJ_SMEM>>>(bq, bk);
    scores_mma_kernel<<<dim3(S_DIM / 128, B_DIM), 256, SCORES_SMEM>>>();
    colreduce_kernel<<<dim3(2, 16, B_DIM), 256>>>();
    pool_kernel<<<dim3(S_DIM / 256, B_DIM), 256>>>(x);
    out_kernel<<<B_DIM, 256>>>(Wv, bv, out);
}

// round 4
// speedup vs baseline: 1.6410x; 1.0495x over previous
#include <cuda_runtime.h>
#include <cuda_bf16.h>
#include <cstdint>

#define B_DIM 4
#define S_DIM 4096
#define E_DIM 256
#define BS_DIM (B_DIM * S_DIM)

// ---------------- scratch (static __device__, no allocations) ----------------
__device__ __nv_bfloat16 g_x_bf[BS_DIM * E_DIM];                  // 8 MB
__device__ __nv_bfloat16 g_WqT[E_DIM * E_DIM];                    // W^T bf16
__device__ __nv_bfloat16 g_WkT[E_DIM * E_DIM];
__device__ __nv_bfloat16 g_q[BS_DIM * E_DIM];                     // 8 MB
__device__ __nv_bfloat16 g_k[BS_DIM * E_DIM];                     // 8 MB
__device__ __nv_bfloat16 g_E[(size_t)B_DIM * S_DIM * S_DIM];      // 134 MB exp-scores
__device__ float g_Z[B_DIM * S_DIM];                              // softmax row sums
__device__ float g_u[B_DIM * S_DIM];                              // column means of attn
__device__ float g_y[B_DIM * E_DIM];                              // u^T x

// ================= low-level helpers =================
__device__ __forceinline__ uint32_t smem_u32(const void* p) {
    uint32_t a;
    asm("{ .reg .u64 t; cvta.to.shared.u64 t, %1; cvt.u32.u64 %0, t; }" : "=r"(a) : "l"(p));
    return a;
}

__device__ __forceinline__ void ldsm4(uint32_t (&r)[4], uint32_t addr) {
    asm volatile("ldmatrix.sync.aligned.m8n8.x4.shared.b16 {%0,%1,%2,%3}, [%4];"
                 : "=r"(r[0]), "=r"(r[1]), "=r"(r[2]), "=r"(r[3]) : "r"(addr));
}

__device__ __forceinline__ void mma16816(float (&d)[4], const uint32_t (&a)[4],
                                         uint32_t b0, uint32_t b1) {
    asm volatile("mma.sync.aligned.m16n8k16.row.col.f32.bf16.bf16.f32 "
                 "{%0,%1,%2,%3}, {%4,%5,%6,%7}, {%8,%9}, {%0,%1,%2,%3};"
                 : "+f"(d[0]), "+f"(d[1]), "+f"(d[2]), "+f"(d[3])
                 : "r"(a[0]), "r"(a[1]), "r"(a[2]), "r"(a[3]), "r"(b0), "r"(b1));
}

// swizzled address inside a 128-row x 256-col bf16 tile (blocked SW128 atoms):
// atom = 8 rows x 128B; atom grid = 16 (rows) x 4 (col-chunks of 64 elems)
__device__ __forceinline__ uint32_t swz128(uint32_t base, int r, int c16) {
    return base + (((uint32_t)(c16 >> 3)) << 14) + (((uint32_t)(r >> 3)) << 10)
                + (((uint32_t)(r & 7)) << 7) + (((uint32_t)((c16 ^ r) & 7)) << 4);
}

// Load a 128x256-bf16 tile (64KB) into the swizzled layout via cp.async (16B chunks).
template <int NT>
__device__ __forceinline__ void load_tile_async(uint32_t sm_base,
                                                const __nv_bfloat16* __restrict__ src,
                                                int tid) {
    #pragma unroll
    for (int it = 0; it < 4096 / NT; ++it) {
        int idx = it * NT + tid;           // 0..4095 16B chunks
        int r = idx >> 5;                  // row 0..127
        int g = idx & 31;                  // chunk 0..31
        uint32_t dst = swz128(sm_base, r, g);
        const void* gp = (const void*)(src + (size_t)r * E_DIM + g * 8);
        asm volatile("cp.async.cg.shared.global [%0], [%1], 16;" :: "r"(dst), "l"(gp));
    }
}
#define CPASYNC_COMMIT() asm volatile("cp.async.commit_group;" ::: "memory")
#define CPASYNC_WAIT0() asm volatile("cp.async.wait_group 0;" ::: "memory")
#define CPASYNC_WAIT1() asm volatile("cp.async.wait_group 1;" ::: "memory")

// warp-tile 32x32 MMA over K=256: acc[2][4][4] += A(rows mw..mw+31) * B(cols nw..nw+31)^T
__device__ __forceinline__ void mma_tile32(uint32_t Ab, uint32_t Bb, float (&acc)[2][4][4],
                                           int mw, int nw, int lane) {
    const int lane15 = lane & 15, laneh = lane >> 4;
    #pragma unroll
    for (int ks = 0; ks < 16; ++ks) {
        const int c16 = ks * 2 + laneh;
        uint32_t a[2][4], bf[2][4];
        #pragma unroll
        for (int i = 0; i < 2; ++i)
            ldsm4(a[i], swz128(Ab, mw + i * 16 + lane15, c16));
        #pragma unroll
        for (int j2 = 0; j2 < 2; ++j2)
            ldsm4(bf[j2], swz128(Bb, nw + j2 * 16 + lane15, c16));
        #pragma unroll
        for (int i = 0; i < 2; ++i)
            #pragma unroll
            for (int j = 0; j < 4; ++j)
                mma16816(acc[i][j], a[i], bf[j >> 1][j & 1], bf[j >> 1][(j & 1) + 2]);
    }
}

// ---------------- fp32 -> bf16 conversion (+ W transposes) + zero-init ----------------
__global__ void convert_kernel(const float* __restrict__ x,
                               const float* __restrict__ Wq,
                               const float* __restrict__ Wk) {
    const int tid = blockIdx.x * blockDim.x + threadIdx.x;
    const int nthr = gridDim.x * blockDim.x;
    // x: 4M floats = 1M uint4
    for (int i = tid; i < (BS_DIM * E_DIM) / 4; i += nthr) {
        float4 f = reinterpret_cast<const float4*>(x)[i];
        __nv_bfloat162 lo = __floats2bfloat162_rn(f.x, f.y);
        __nv_bfloat162 hi = __floats2bfloat162_rn(f.z, f.w);
        uint2 pkt;
        pkt.x = *reinterpret_cast<uint32_t*>(&lo);
        pkt.y = *reinterpret_cast<uint32_t*>(&hi);
        reinterpret_cast<uint2*>(g_x_bf)[i] = pkt;
    }
    if (tid < E_DIM * E_DIM) {
        int k = tid >> 8, n = tid & 255;
        g_WqT[n * E_DIM + k] = __float2bfloat16(Wq[tid]);
        g_WkT[n * E_DIM + k] = __float2bfloat16(Wk[tid]);
    }
    if (tid < B_DIM * S_DIM) { g_Z[tid] = 0.f; g_u[tid] = 0.f; }
    if (tid < B_DIM * E_DIM) g_y[tid] = 0.f;
}

// ---------------- Q/K projections: out = bf16(x @ W + b) ----------------
// grid (BS/128, 2, 2): (m-block, n-block, which). One-shot tile, K=256.
#define PROJ_SMEM (131072 + 1024)
__global__ void __launch_bounds__(256) proj_tc_kernel(const float* __restrict__ bq,
                                                      const float* __restrict__ bk) {
    extern __shared__ char dynsm[];
    __shared__ float sbias[128];
    const uint32_t base = (smem_u32(dynsm) + 1023u) & ~1023u;
    const uint32_t Ab = base, Bb = base + 65536u;

    const int tid = threadIdx.x;
    const int lane = tid & 31, wid = tid >> 5;
    const int mw = (wid & 1) * 64, nw = (wid >> 1) * 32;
    const int m0 = blockIdx.x * 128, n0 = blockIdx.y * 128;
    const int which = blockIdx.z;

    const __nv_bfloat16* WT = which ? g_WkT : g_WqT;
    const float* bias = which ? bk : bq;
    __nv_bfloat16* outp = which ? g_k : g_q;

    if (tid < 128) sbias[tid] = bias[n0 + tid];
    load_tile_async<256>(Ab, g_x_bf + (size_t)m0 * E_DIM, tid);
    load_tile_async<256>(Bb, WT + (size_t)n0 * E_DIM, tid);
    CPASYNC_COMMIT();
    CPASYNC_WAIT0();
    __syncthreads();

    // warp tile 64x32: two 32x32 halves sharing B fragments
    float acc[2][2][4][4];
    #pragma unroll
    for (int mh = 0; mh < 2; ++mh)
        #pragma unroll
        for (int i = 0; i < 2; ++i)
            #pragma unroll
            for (int j = 0; j < 4; ++j)
                #pragma unroll
                for (int v = 0; v < 4; ++v) acc[mh][i][j][v] = 0.f;
    #pragma unroll
    for (int mh = 0; mh < 2; ++mh)
        mma_tile32(Ab, Bb, acc[mh], mw + mh * 32, nw, lane);

    #pragma unroll
    for (int mh = 0; mh < 2; ++mh) {
        #pragma unroll
        for (int i = 0; i < 2; ++i) {
            #pragma unroll
            for (int h = 0; h < 2; ++h) {
                const int r = m0 + mw + mh * 32 + i * 16 + (lane >> 2) + h * 8;
                #pragma unroll
                for (int j = 0; j < 4; ++j) {
                    const int cl = nw + j * 8 + (lane & 3) * 2;
                    float v0 = acc[mh][i][j][2 * h]     + sbias[cl];
                    float v1 = acc[mh][i][j][2 * h + 1] + sbias[cl + 1];
                    *reinterpret_cast<__nv_bfloat162*>(&outp[(size_t)r * E_DIM + n0 + cl]) =
                        __floats2bfloat162_rn(v0, v1);
                }
            }
        }
    }
}

// ---------------- scores: E = exp(q k^T / 16), fused row sums -> g_Z ----------------
// grid (32, 4): (m-block of 128 rows, batch). Loops 32 n-tiles of 128 cols.
// 512 threads, 16 warps in 4x4 grid, warp tile 32x32.
// SMEM: A 64KB resident + B double-buffered 2x64KB.
#define SCORES_SMEM (196608 + 1024)
__global__ void __launch_bounds__(512, 1) scores_mma_kernel() {
    extern __shared__ char dynsm[];
    const uint32_t base = (smem_u32(dynsm) + 1023u) & ~1023u;
    const uint32_t Ab = base;
    const uint32_t Bbuf[2] = { base + 65536u, base + 131072u };

    const int tid = threadIdx.x;
    const int lane = tid & 31, wid = tid >> 5;
    const int mw = (wid & 3) * 32, nw = (wid >> 2) * 32;
    const int m0 = blockIdx.x * 128;
    const int b = blockIdx.y;

    const __nv_bfloat16* Aq = g_q + (size_t)b * S_DIM * E_DIM;
    const __nv_bfloat16* Bk = g_k + (size_t)b * S_DIM * E_DIM;

    load_tile_async<512>(Ab, Aq + (size_t)m0 * E_DIM, tid);
    load_tile_async<512>(Bbuf[0], Bk, tid);
    CPASYNC_COMMIT();

    float rs[4];
    #pragma unroll
    for (int i = 0; i < 4; ++i) rs[i] = 0.f;

    const float SCALE = 0.09016844f;  // log2(e) / 16

    #pragma unroll 1
    for (int n = 0; n < 32; ++n) {
        if (n + 1 < 32) {
            load_tile_async<512>(Bbuf[(n + 1) & 1], Bk + (size_t)(n + 1) * 128 * E_DIM, tid);
            CPASYNC_COMMIT();
            CPASYNC_WAIT1();
        } else {
            CPASYNC_WAIT0();
        }
        __syncthreads();

        float acc[2][4][4];
        #pragma unroll
        for (int i = 0; i < 2; ++i)
            #pragma unroll
            for (int j = 0; j < 4; ++j)
                #pragma unroll
                for (int v = 0; v < 4; ++v) acc[i][j][v] = 0.f;

        mma_tile32(Ab, Bbuf[n & 1], acc, mw, nw, lane);

        // epilogue: exp(score/16) -> bf16 store + row-sum accumulation
        #pragma unroll
        for (int i = 0; i < 2; ++i) {
            #pragma unroll
            for (int h = 0; h < 2; ++h) {
                const int r = m0 + mw + i * 16 + (lane >> 2) + h * 8;
                const size_t rowb = ((size_t)b * S_DIM + r) * S_DIM
                                  + (size_t)n * 128 + nw + (lane & 3) * 2;
                float partial = 0.f;
                #pragma unroll
                for (int j = 0; j < 4; ++j) {
                    float v0, v1;
                    asm("ex2.approx.ftz.f32 %0, %1;" : "=f"(v0) : "f"(acc[i][j][2 * h] * SCALE));
                    asm("ex2.approx.ftz.f32 %0, %1;" : "=f"(v1) : "f"(acc[i][j][2 * h + 1] * SCALE));
                    partial += v0 + v1;
                    *reinterpret_cast<__nv_bfloat162*>(&g_E[rowb + j * 8]) =
                        __floats2bfloat162_rn(v0, v1);
                }
                rs[i * 2 + h] += partial;
            }
        }
        __syncthreads();
    }

    // reduce row sums over the 4 lanes sharing a row, then atomically publish
    #pragma unroll
    for (int i = 0; i < 4; ++i) {
        rs[i] += __shfl_xor_sync(0xffffffffu, rs[i], 1);
        rs[i] += __shfl_xor_sync(0xffffffffu, rs[i], 2);
    }
    if ((lane & 3) == 0) {
        #pragma unroll
        for (int i = 0; i < 4; ++i) {
            const int r = m0 + mw + (i >> 1) * 16 + (i & 1) * 8 + (lane >> 2);
            atomicAdd(&g_Z[b * S_DIM + r], rs[i]);
        }
    }
}

// ---------------- u[b,t] = (1/S) * sum_s E[b,s,t] / Z[b,s] ----------------
__global__ void __launch_bounds__(256) colreduce_kernel() {
    const int b  = blockIdx.z;
    const int s0 = blockIdx.y * 256;
    const int t0 = blockIdx.x * 2048 + threadIdx.x * 8;
    __shared__ float invZ[256];
    invZ[threadIdx.x] = 1.f / g_Z[b * S_DIM + s0 + threadIdx.x];
    __syncthreads();
    float a[8] = {0.f, 0.f, 0.f, 0.f, 0.f, 0.f, 0.f, 0.f};
    const __nv_bfloat16* Ep = g_E + ((size_t)b * S_DIM + s0) * S_DIM + t0;
    #pragma unroll 8
    for (int s = 0; s < 256; ++s) {
        uint4 pkt = *reinterpret_cast<const uint4*>(&Ep[(size_t)s * S_DIM]);
        const __nv_bfloat162* p2 = reinterpret_cast<const __nv_bfloat162*>(&pkt);
        float w = invZ[s];
        #pragma unroll
        for (int j = 0; j < 4; ++j) {
            float2 f = __bfloat1622float2(p2[j]);
            a[2 * j]     += f.x * w;
            a[2 * j + 1] += f.y * w;
        }
    }
    const float sc = 1.f / S_DIM;
    #pragma unroll
    for (int j = 0; j < 8; ++j)
        atomicAdd(&g_u[b * S_DIM + t0 + j], a[j] * sc);
}

// ---------------- y[b,:] = sum_t u[b,t] * x[b,t,:]  (fp32-exact V path) ----------------
__global__ void __launch_bounds__(256) pool_kernel(const float* __restrict__ x) {
    const int b = blockIdx.y, seg = blockIdx.x;
    const int e = threadIdx.x;
    __shared__ float us[256];
    us[e] = g_u[b * S_DIM + seg * 256 + e];
    __syncthreads();
    float acc = 0.f;
    const float* xp = x + ((size_t)b * S_DIM + seg * 256) * E_DIM + e;
    #pragma unroll 8
    for (int tt = 0; tt < 256; ++tt) acc += us[tt] * xp[(size_t)tt * E_DIM];
    atomicAdd(&g_y[b * E_DIM + e], acc);
}

// ---------------- out[b,:] = y[b,:] @ Wv + bv ----------------
__global__ void __launch_bounds__(256) out_kernel(const float* __restrict__ Wv,
                                                  const float* __restrict__ bv,
                                                  float* __restrict__ out) {
    const int b = blockIdx.x, e = threadIdx.x;
    __shared__ float ys[256];
    ys[e] = g_y[b * E_DIM + e];
    __syncthreads();
    float acc = 0.f;
    #pragma unroll 8
    for (int j = 0; j < 256; ++j) acc += ys[j] * Wv[j * E_DIM + e];
    out[b * E_DIM + e] = acc + bv[e];
}

// ---------------- launch ----------------
extern "C" void kernel_launch(void* const* d_in, const int* in_sizes, int n_in,
                              void* d_out, int out_size) {
    (void)in_sizes; (void)n_in; (void)out_size;
    const float* x  = (const float*)d_in[0];
    const float* Wq = (const float*)d_in[1];
    const float* bq = (const float*)d_in[2];
    const float* Wk = (const float*)d_in[3];
    const float* bk = (const float*)d_in[4];
    const float* Wv = (const float*)d_in[5];
    const float* bv = (const float*)d_in[6];
    float* out = (float*)d_out;

    cudaFuncSetAttribute(scores_mma_kernel,
                         cudaFuncAttributeMaxDynamicSharedMemorySize, SCORES_SMEM);
    cudaFuncSetAttribute(proj_tc_kernel,
                         cudaFuncAttributeMaxDynamicSharedMemorySize, PROJ_SMEM);

    convert_kernel<<<1024, 256>>>(x, Wq, Wk);
    proj_tc_kernel<<<dim3(BS_DIM / 128, 2, 2), 256, PROJ_SMEM>>>(bq, bk);
    scores_mma_kernel<<<dim3(S_DIM / 128, B_DIM), 512, SCORES_SMEM>>>();
    colreduce_kernel<<<dim3(2, 16, B_DIM), 256>>>();
    pool_kernel<<<dim3(S_DIM / 256, B_DIM), 256>>>(x);
    out_kernel<<<B_DIM, 256>>>(Wv, bv, out);
}

// round 5
// speedup vs baseline: 1.9905x; 1.2130x over previous
#include <cuda_runtime.h>
#include <cuda_bf16.h>
#include <cstdint>

#define B_DIM 4
#define S_DIM 4096
#define E_DIM 256
#define BS_DIM (B_DIM * S_DIM)

// ---------------- scratch (static __device__, no allocations) ----------------
__device__ __nv_bfloat16 g_x_bf[BS_DIM * E_DIM];                  // 8 MB
__device__ __nv_bfloat16 g_WqT[E_DIM * E_DIM];                    // W^T bf16
__device__ __nv_bfloat16 g_WkT[E_DIM * E_DIM];
__device__ __nv_bfloat16 g_q[BS_DIM * E_DIM];                     // 8 MB
__device__ __nv_bfloat16 g_k[BS_DIM * E_DIM];                     // 8 MB
__device__ __nv_bfloat16 g_E[(size_t)B_DIM * S_DIM * S_DIM];      // 134 MB exp-scores
__device__ float g_Z[B_DIM * S_DIM];                              // softmax row sums
__device__ float g_u[B_DIM * S_DIM];                              // column means of attn
__device__ float g_y[B_DIM * E_DIM];                              // u^T x

// ================= low-level helpers =================
__device__ __forceinline__ uint32_t smem_u32(const void* p) {
    uint32_t a;
    asm("{ .reg .u64 t; cvta.to.shared.u64 t, %1; cvt.u32.u64 %0, t; }" : "=r"(a) : "l"(p));
    return a;
}

__device__ __forceinline__ void ldsm4(uint32_t (&r)[4], uint32_t addr) {
    asm volatile("ldmatrix.sync.aligned.m8n8.x4.shared.b16 {%0,%1,%2,%3}, [%4];"
                 : "=r"(r[0]), "=r"(r[1]), "=r"(r[2]), "=r"(r[3]) : "r"(addr));
}

__device__ __forceinline__ void mma16816(float (&d)[4], const uint32_t (&a)[4],
                                         uint32_t b0, uint32_t b1) {
    asm volatile("mma.sync.aligned.m16n8k16.row.col.f32.bf16.bf16.f32 "
                 "{%0,%1,%2,%3}, {%4,%5,%6,%7}, {%8,%9}, {%0,%1,%2,%3};"
                 : "+f"(d[0]), "+f"(d[1]), "+f"(d[2]), "+f"(d[3])
                 : "r"(a[0]), "r"(a[1]), "r"(a[2]), "r"(a[3]), "r"(b0), "r"(b1));
}

// swizzled address inside a 128-row x 256-col bf16 tile (blocked SW128 atoms):
// atom = 8 rows x 128B; atom grid = 16 (rows) x 4 (col-chunks of 64 elems)
__device__ __forceinline__ uint32_t swz128(uint32_t base, int r, int c16) {
    return base + (((uint32_t)(c16 >> 3)) << 14) + (((uint32_t)(r >> 3)) << 10)
                + (((uint32_t)(r & 7)) << 7) + (((uint32_t)((c16 ^ r) & 7)) << 4);
}

// Load a 128x256-bf16 tile (64KB) into the swizzled layout via cp.async (16B chunks).
template <int NT>
__device__ __forceinline__ void load_tile_async(uint32_t sm_base,
                                                const __nv_bfloat16* __restrict__ src,
                                                int tid) {
    #pragma unroll
    for (int it = 0; it < 4096 / NT; ++it) {
        int idx = it * NT + tid;           // 0..4095 16B chunks
        int r = idx >> 5;                  // row 0..127
        int g = idx & 31;                  // chunk 0..31
        uint32_t dst = swz128(sm_base, r, g);
        const void* gp = (const void*)(src + (size_t)r * E_DIM + g * 8);
        asm volatile("cp.async.cg.shared.global [%0], [%1], 16;" :: "r"(dst), "l"(gp));
    }
}
#define CPASYNC_COMMIT() asm volatile("cp.async.commit_group;" ::: "memory")
#define CPASYNC_WAIT0() asm volatile("cp.async.wait_group 0;" ::: "memory")

// warp-tile 32x32 MMA over K=256: acc[2][4][4] += A(rows mw..mw+31) * B(cols nw..nw+31)^T
__device__ __forceinline__ void mma_tile32(uint32_t Ab, uint32_t Bb, float (&acc)[2][4][4],
                                           int mw, int nw, int lane) {
    const int lane15 = lane & 15, laneh = lane >> 4;
    #pragma unroll
    for (int ks = 0; ks < 16; ++ks) {
        const int c16 = ks * 2 + laneh;
        uint32_t a[2][4], bf[2][4];
        #pragma unroll
        for (int i = 0; i < 2; ++i)
            ldsm4(a[i], swz128(Ab, mw + i * 16 + lane15, c16));
        #pragma unroll
        for (int j2 = 0; j2 < 2; ++j2)
            ldsm4(bf[j2], swz128(Bb, nw + j2 * 16 + lane15, c16));
        #pragma unroll
        for (int i = 0; i < 2; ++i)
            #pragma unroll
            for (int j = 0; j < 4; ++j)
                mma16816(acc[i][j], a[i], bf[j >> 1][j & 1], bf[j >> 1][(j & 1) + 2]);
    }
}

// ---------------- fp32 -> bf16 conversion (+ W transposes) + zero-init ----------------
__global__ void convert_kernel(const float* __restrict__ x,
                               const float* __restrict__ Wq,
                               const float* __restrict__ Wk) {
    const int tid = blockIdx.x * blockDim.x + threadIdx.x;
    const int nthr = gridDim.x * blockDim.x;
    for (int i = tid; i < (BS_DIM * E_DIM) / 4; i += nthr) {
        float4 f = reinterpret_cast<const float4*>(x)[i];
        __nv_bfloat162 lo = __floats2bfloat162_rn(f.x, f.y);
        __nv_bfloat162 hi = __floats2bfloat162_rn(f.z, f.w);
        uint2 pkt;
        pkt.x = *reinterpret_cast<uint32_t*>(&lo);
        pkt.y = *reinterpret_cast<uint32_t*>(&hi);
        reinterpret_cast<uint2*>(g_x_bf)[i] = pkt;
    }
    if (tid < E_DIM * E_DIM) {
        int k = tid >> 8, n = tid & 255;
        g_WqT[n * E_DIM + k] = __float2bfloat16(Wq[tid]);
        g_WkT[n * E_DIM + k] = __float2bfloat16(Wk[tid]);
    }
    if (tid < B_DIM * S_DIM) { g_Z[tid] = 0.f; g_u[tid] = 0.f; }
    if (tid < B_DIM * E_DIM) g_y[tid] = 0.f;
}

// ---------------- Q/K projections: out = bf16(x @ W + b) ----------------
#define PROJ_SMEM (131072 + 1024)
__global__ void __launch_bounds__(256) proj_tc_kernel(const float* __restrict__ bq,
                                                      const float* __restrict__ bk) {
    extern __shared__ char dynsm[];
    __shared__ float sbias[128];
    const uint32_t base = (smem_u32(dynsm) + 1023u) & ~1023u;
    const uint32_t Ab = base, Bb = base + 65536u;

    const int tid = threadIdx.x;
    const int lane = tid & 31, wid = tid >> 5;
    const int mw = (wid & 1) * 64, nw = (wid >> 1) * 32;
    const int m0 = blockIdx.x * 128, n0 = blockIdx.y * 128;
    const int which = blockIdx.z;

    const __nv_bfloat16* WT = which ? g_WkT : g_WqT;
    const float* bias = which ? bk : bq;
    __nv_bfloat16* outp = which ? g_k : g_q;

    if (tid < 128) sbias[tid] = bias[n0 + tid];
    load_tile_async<256>(Ab, g_x_bf + (size_t)m0 * E_DIM, tid);
    load_tile_async<256>(Bb, WT + (size_t)n0 * E_DIM, tid);
    CPASYNC_COMMIT();
    CPASYNC_WAIT0();
    __syncthreads();

    float acc[2][2][4][4];
    #pragma unroll
    for (int mh = 0; mh < 2; ++mh)
        #pragma unroll
        for (int i = 0; i < 2; ++i)
            #pragma unroll
            for (int j = 0; j < 4; ++j)
                #pragma unroll
                for (int v = 0; v < 4; ++v) acc[mh][i][j][v] = 0.f;
    #pragma unroll
    for (int mh = 0; mh < 2; ++mh)
        mma_tile32(Ab, Bb, acc[mh], mw + mh * 32, nw, lane);

    #pragma unroll
    for (int mh = 0; mh < 2; ++mh) {
        #pragma unroll
        for (int i = 0; i < 2; ++i) {
            #pragma unroll
            for (int h = 0; h < 2; ++h) {
                const int r = m0 + mw + mh * 32 + i * 16 + (lane >> 2) + h * 8;
                #pragma unroll
                for (int j = 0; j < 4; ++j) {
                    const int cl = nw + j * 8 + (lane & 3) * 2;
                    float v0 = acc[mh][i][j][2 * h]     + sbias[cl];
                    float v1 = acc[mh][i][j][2 * h + 1] + sbias[cl + 1];
                    *reinterpret_cast<__nv_bfloat162*>(&outp[(size_t)r * E_DIM + n0 + cl]) =
                        __floats2bfloat162_rn(v0, v1);
                }
            }
        }
    }
}

// ---------------- scores: E = exp(q k^T / 16), fused row sums -> g_Z ----------------
// grid (32, 4). 512 threads, 16 warps in 4x4 grid, warp tile 32x32.
// Single-sync double-buffer: prefetch of tile n+1 issued AFTER the barrier, so the
// end-of-iteration barrier is unnecessary (all warps are past iteration n-1).
#define SCORES_SMEM (196608 + 1024)
__global__ void __launch_bounds__(512, 1) scores_mma_kernel() {
    extern __shared__ char dynsm[];
    const uint32_t base = (smem_u32(dynsm) + 1023u) & ~1023u;
    const uint32_t Ab = base;
    const uint32_t Bbuf[2] = { base + 65536u, base + 131072u };

    const int tid = threadIdx.x;
    const int lane = tid & 31, wid = tid >> 5;
    const int mw = (wid & 3) * 32, nw = (wid >> 2) * 32;
    const int m0 = blockIdx.x * 128;
    const int b = blockIdx.y;

    const __nv_bfloat16* Aq = g_q + (size_t)b * S_DIM * E_DIM;
    const __nv_bfloat16* Bk = g_k + (size_t)b * S_DIM * E_DIM;

    load_tile_async<512>(Ab, Aq + (size_t)m0 * E_DIM, tid);
    load_tile_async<512>(Bbuf[0], Bk, tid);
    CPASYNC_COMMIT();

    float rs[4];
    #pragma unroll
    for (int i = 0; i < 4; ++i) rs[i] = 0.f;

    const float SCALE = 0.09016844f;  // log2(e) / 16

    #pragma unroll 1
    for (int n = 0; n < 32; ++n) {
        CPASYNC_WAIT0();
        __syncthreads();
        if (n + 1 < 32) {
            load_tile_async<512>(Bbuf[(n + 1) & 1], Bk + (size_t)(n + 1) * 128 * E_DIM, tid);
            CPASYNC_COMMIT();
        }

        float acc[2][4][4];
        #pragma unroll
        for (int i = 0; i < 2; ++i)
            #pragma unroll
            for (int j = 0; j < 4; ++j)
                #pragma unroll
                for (int v = 0; v < 4; ++v) acc[i][j][v] = 0.f;

        mma_tile32(Ab, Bbuf[n & 1], acc, mw, nw, lane);

        // epilogue: exp(score/16) -> bf16 store + row-sum accumulation
        #pragma unroll
        for (int i = 0; i < 2; ++i) {
            #pragma unroll
            for (int h = 0; h < 2; ++h) {
                const int r = m0 + mw + i * 16 + (lane >> 2) + h * 8;
                const size_t rowb = ((size_t)b * S_DIM + r) * S_DIM
                                  + (size_t)n * 128 + nw + (lane & 3) * 2;
                float partial = 0.f;
                #pragma unroll
                for (int j = 0; j < 4; ++j) {
                    float v0, v1;
                    asm("ex2.approx.ftz.f32 %0, %1;" : "=f"(v0) : "f"(acc[i][j][2 * h] * SCALE));
                    asm("ex2.approx.ftz.f32 %0, %1;" : "=f"(v1) : "f"(acc[i][j][2 * h + 1] * SCALE));
                    partial += v0 + v1;
                    *reinterpret_cast<__nv_bfloat162*>(&g_E[rowb + j * 8]) =
                        __floats2bfloat162_rn(v0, v1);
                }
                rs[i * 2 + h] += partial;
            }
        }
    }

    // reduce row sums over the 4 lanes sharing a row, then atomically publish
    #pragma unroll
    for (int i = 0; i < 4; ++i) {
        rs[i] += __shfl_xor_sync(0xffffffffu, rs[i], 1);
        rs[i] += __shfl_xor_sync(0xffffffffu, rs[i], 2);
    }
    if ((lane & 3) == 0) {
        #pragma unroll
        for (int i = 0; i < 4; ++i) {
            const int r = m0 + mw + (i >> 1) * 16 + (i & 1) * 8 + (lane >> 2);
            atomicAdd(&g_Z[b * S_DIM + r], rs[i]);
        }
    }
}

// ---------------- u[b,t] = (1/S) * sum_s E[b,s,t] / Z[b,s] ----------------
// grid (2, 64, 4) = 512 CTAs; s-chunk 64 rows; thread handles 8 consecutive t.
__global__ void __launch_bounds__(256) colreduce_kernel() {
    const int b  = blockIdx.z;
    const int s0 = blockIdx.y * 64;
    const int t0 = blockIdx.x * 2048 + threadIdx.x * 8;
    __shared__ float invZ[64];
    if (threadIdx.x < 64)
        invZ[threadIdx.x] = 1.f / g_Z[b * S_DIM + s0 + threadIdx.x];
    __syncthreads();
    float a[8] = {0.f, 0.f, 0.f, 0.f, 0.f, 0.f, 0.f, 0.f};
    const __nv_bfloat16* Ep = g_E + ((size_t)b * S_DIM + s0) * S_DIM + t0;
    #pragma unroll 8
    for (int s = 0; s < 64; ++s) {
        uint4 pkt = *reinterpret_cast<const uint4*>(&Ep[(size_t)s * S_DIM]);
        const __nv_bfloat162* p2 = reinterpret_cast<const __nv_bfloat162*>(&pkt);
        float w = invZ[s];
        #pragma unroll
        for (int j = 0; j < 4; ++j) {
            float2 f = __bfloat1622float2(p2[j]);
            a[2 * j]     += f.x * w;
            a[2 * j + 1] += f.y * w;
        }
    }
    const float sc = 1.f / S_DIM;
    #pragma unroll
    for (int j = 0; j < 8; ++j)
        atomicAdd(&g_u[b * S_DIM + t0 + j], a[j] * sc);
}

// ---------------- y[b,:] = sum_t u[b,t] * x[b,t,:]  (fp32-exact V path) ----------------
// grid (32, 4): 128-row segments for occupancy.
__global__ void __launch_bounds__(256) pool_kernel(const float* __restrict__ x) {
    const int b = blockIdx.y, seg = blockIdx.x;
    const int e = threadIdx.x;
    __shared__ float us[128];
    if (e < 128) us[e] = g_u[b * S_DIM + seg * 128 + e];
    __syncthreads();
    float acc = 0.f;
    const float* xp = x + ((size_t)b * S_DIM + seg * 128) * E_DIM + e;
    #pragma unroll 8
    for (int tt = 0; tt < 128; ++tt) acc += us[tt] * xp[(size_t)tt * E_DIM];
    atomicAdd(&g_y[b * E_DIM + e], acc);
}

// ---------------- out[b,:] = y[b,:] @ Wv + bv ----------------
__global__ void __launch_bounds__(256) out_kernel(const float* __restrict__ Wv,
                                                  const float* __restrict__ bv,
                                                  float* __restrict__ out) {
    const int b = blockIdx.x, e = threadIdx.x;
    __shared__ float ys[256];
    ys[e] = g_y[b * E_DIM + e];
    __syncthreads();
    float acc = 0.f;
    #pragma unroll 8
    for (int j = 0; j < 256; ++j) acc += ys[j] * Wv[j * E_DIM + e];
    out[b * E_DIM + e] = acc + bv[e];
}

// ---------------- launch ----------------
extern "C" void kernel_launch(void* const* d_in, const int* in_sizes, int n_in,
                              void* d_out, int out_size) {
    (void)in_sizes; (void)n_in; (void)out_size;
    const float* x  = (const float*)d_in[0];
    const float* Wq = (const float*)d_in[1];
    const float* bq = (const float*)d_in[2];
    const float* Wk = (const float*)d_in[3];
    const float* bk = (const float*)d_in[4];
    const float* Wv = (const float*)d_in[5];
    const float* bv = (const float*)d_in[6];
    float* out = (float*)d_out;

    cudaFuncSetAttribute(scores_mma_kernel,
                         cudaFuncAttributeMaxDynamicSharedMemorySize, SCORES_SMEM);
    cudaFuncSetAttribute(proj_tc_kernel,
                         cudaFuncAttributeMaxDynamicSharedMemorySize, PROJ_SMEM);

    convert_kernel<<<1024, 256>>>(x, Wq, Wk);
    proj_tc_kernel<<<dim3(BS_DIM / 128, 2, 2), 256, PROJ_SMEM>>>(bq, bk);
    scores_mma_kernel<<<dim3(S_DIM / 128, B_DIM), 512, SCORES_SMEM>>>();
    colreduce_kernel<<<dim3(2, 64, B_DIM), 256>>>();
    pool_kernel<<<dim3(S_DIM / 128, B_DIM), 256>>>(x);
    out_kernel<<<B_DIM, 256>>>(Wv, bv, out);
}